// round 6
// baseline (speedup 1.0000x reference)
#include <cuda_runtime.h>
#include <math.h>
#include <stdint.h>

#define T_SEQ   2048
#define BATCH   2
#define DMODEL  1024
#define NHEADS  16
#define DHEAD   64
#define MROWS   (BATCH * T_SEQ)   // 4096
#define PI_F    3.14159265358979323846f

// ---------------- device scratch (no allocations allowed) ----------------
__device__ float g_q [MROWS * DMODEL];
__device__ float g_k [MROWS * DMODEL];
__device__ float g_v [MROWS * DMODEL];
__device__ float g_ao[MROWS * DMODEL];

// =========================================================================
// SGEMM (NT):  C[m,n] = sum_k A[m*K+k] * B[n*K+k]
// 64x64 tile, BK=16, 128 threads, 8x4 microtile per thread.
// Both A and B are row-major with K contiguous (exactly x @ W^T).
// =========================================================================
__global__ __launch_bounds__(128)
void sgemm_nt64(const float* __restrict__ A, const float* __restrict__ B,
                float* __restrict__ C, int M, int N, int K)
{
    __shared__ float As[16][68];   // [k][m] transposed, padded
    __shared__ float Bs[16][68];   // [k][n] transposed, padded

    const int tid = threadIdx.x;
    const int tx  = tid & 15;      // 0..15 -> 4 output cols each
    const int ty  = tid >> 4;      // 0..7  -> 8 output rows each
    const int bm  = blockIdx.y << 6;
    const int bn  = blockIdx.x << 6;

    const int r_a = tid >> 2;          // base load row (0..31), +32 on 2nd pass
    const int kq  = (tid & 3) << 2;    // k quad 0,4,8,12

    float acc[8][4];
#pragma unroll
    for (int i = 0; i < 8; i++)
#pragma unroll
        for (int j = 0; j < 4; j++) acc[i][j] = 0.f;

    for (int k0 = 0; k0 < K; k0 += 16) {
#pragma unroll
        for (int i = 0; i < 2; i++) {
            int row = r_a + (i << 5);
            float4 va = *(const float4*)(A + (size_t)(bm + row) * K + k0 + kq);
            As[kq + 0][row] = va.x; As[kq + 1][row] = va.y;
            As[kq + 2][row] = va.z; As[kq + 3][row] = va.w;
            float4 vb = *(const float4*)(B + (size_t)(bn + row) * K + k0 + kq);
            Bs[kq + 0][row] = vb.x; Bs[kq + 1][row] = vb.y;
            Bs[kq + 2][row] = vb.z; Bs[kq + 3][row] = vb.w;
        }
        __syncthreads();

#pragma unroll
        for (int k = 0; k < 16; k++) {
            float4 a0 = *(const float4*)&As[k][ty * 8];
            float4 a1 = *(const float4*)&As[k][ty * 8 + 4];
            float4 b0 = *(const float4*)&Bs[k][tx * 4];
            float ar[8] = {a0.x, a0.y, a0.z, a0.w, a1.x, a1.y, a1.z, a1.w};
            float br[4] = {b0.x, b0.y, b0.z, b0.w};
#pragma unroll
            for (int i = 0; i < 8; i++)
#pragma unroll
                for (int j = 0; j < 4; j++)
                    acc[i][j] += ar[i] * br[j];
        }
        __syncthreads();
    }

#pragma unroll
    for (int i = 0; i < 8; i++) {
        int row = bm + ty * 8 + i;
        float4 v = make_float4(acc[i][0], acc[i][1], acc[i][2], acc[i][3]);
        *(float4*)(C + (size_t)row * N + bn + tx * 4) = v;
    }
}

// =========================================================================
// Flash attention + rotation/valve epilogue.
// Block: 64 query rows of one (b, h). 256 threads.
// 64-key tiles; online softmax fully in registers (row groups align with
// 16-lane shuffle halves). P goes through smem only for the PV matmul.
// Epilogue: o /= l, then rot(x*iv)*ov*g with per-head constant angle,
// written directly in the [B,T,D] combined layout.
// =========================================================================
#define PS 68   // smem row stride (floats): 16B-aligned float4s, low conflicts

__global__ __launch_bounds__(256)
void attn_kernel(const float* __restrict__ Q, const float* __restrict__ Kg,
                 const float* __restrict__ Vg,
                 const float* __restrict__ beta_, const float* __restrict__ inval,
                 const float* __restrict__ outval, const float* __restrict__ chiv,
                 float* __restrict__ out)
{
    extern __shared__ float sm[];
    float* Qs = sm;                 // [d][row]   64 x PS
    float* Ks = sm + 64 * PS;       // [d][key]   64 x PS
    float* Vs = sm + 2 * 64 * PS;   // [key][d]   64 x PS
    float* Ss = sm + 3 * 64 * PS;   // [key][row] 64 x PS (reused as Os[row][col])

    const int h   = blockIdx.y;
    const int b   = blockIdx.z;
    const int q0  = blockIdx.x << 6;
    const int tid = threadIdx.x;
    const int tx  = tid & 15;
    const int tyf = tid >> 4;            // 0..15
    const int r0  = tyf << 2;            // 4 query rows
    const int c0  = tx << 2;             // 4 key cols (S) / 4 dh cols (PV)

    const float* qb = Q  + ((size_t)(b * T_SEQ + q0)) * DMODEL + h * DHEAD;
    const float* kb = Kg + ((size_t)(b * T_SEQ))      * DMODEL + h * DHEAD;
    const float* vb = Vg + ((size_t)(b * T_SEQ))      * DMODEL + h * DHEAD;

    const int lrow = tid >> 4;           // load row base (0..15), +16 per pass
    const int ldq  = (tid & 15) << 2;    // load dq (0..60)

    // ---- load Q tile transposed: Qs[d][row] ----
#pragma unroll
    for (int i = 0; i < 4; i++) {
        int row = lrow + (i << 4);
        float4 v = *(const float4*)(qb + (size_t)row * DMODEL + ldq);
        Qs[(ldq + 0) * PS + row] = v.x;
        Qs[(ldq + 1) * PS + row] = v.y;
        Qs[(ldq + 2) * PS + row] = v.z;
        Qs[(ldq + 3) * PS + row] = v.w;
    }

    float m_i[4] = {-1e30f, -1e30f, -1e30f, -1e30f};
    float l_i[4] = {0.f, 0.f, 0.f, 0.f};
    float o[4][4];
#pragma unroll
    for (int i = 0; i < 4; i++)
#pragma unroll
        for (int j = 0; j < 4; j++) o[i][j] = 0.f;

    for (int kt = 0; kt < T_SEQ / 64; kt++) {
        __syncthreads();   // previous PV done before overwriting K/V tiles
        const float* kbt = kb + (size_t)kt * 64 * DMODEL;
        const float* vbt = vb + (size_t)kt * 64 * DMODEL;
#pragma unroll
        for (int i = 0; i < 4; i++) {
            int row = lrow + (i << 4);
            float4 v = *(const float4*)(kbt + (size_t)row * DMODEL + ldq);
            Ks[(ldq + 0) * PS + row] = v.x;
            Ks[(ldq + 1) * PS + row] = v.y;
            Ks[(ldq + 2) * PS + row] = v.z;
            Ks[(ldq + 3) * PS + row] = v.w;
            float4 w = *(const float4*)(vbt + (size_t)row * DMODEL + ldq);
            *(float4*)(Vs + row * PS + ldq) = w;
        }
        __syncthreads();

        // ---- S = Q K^T fragment (4x4) ----
        float s[4][4];
#pragma unroll
        for (int i = 0; i < 4; i++)
#pragma unroll
            for (int j = 0; j < 4; j++) s[i][j] = 0.f;

#pragma unroll 8
        for (int d = 0; d < 64; d++) {
            float4 a  = *(const float4*)(Qs + d * PS + r0);
            float4 bb = *(const float4*)(Ks + d * PS + c0);
            float ar[4] = {a.x, a.y, a.z, a.w};
            float br[4] = {bb.x, bb.y, bb.z, bb.w};
#pragma unroll
            for (int i = 0; i < 4; i++)
#pragma unroll
                for (int j = 0; j < 4; j++)
                    s[i][j] += ar[i] * br[j];
        }

        // ---- online softmax, register resident (reduce over 16-lane half) ----
#pragma unroll
        for (int i = 0; i < 4; i++) {
#pragma unroll
            for (int j = 0; j < 4; j++) s[i][j] *= 0.125f;   // 1/sqrt(dh*conv)
            float mx = fmaxf(fmaxf(s[i][0], s[i][1]), fmaxf(s[i][2], s[i][3]));
#pragma unroll
            for (int off = 8; off > 0; off >>= 1)
                mx = fmaxf(mx, __shfl_xor_sync(0xffffffffu, mx, off));
            float nm = fmaxf(m_i[i], mx);
            float al = __expf(m_i[i] - nm);
            float ps = 0.f;
#pragma unroll
            for (int j = 0; j < 4; j++) {
                float p = __expf(s[i][j] - nm);
                s[i][j] = p;
                ps += p;
            }
#pragma unroll
            for (int off = 8; off > 0; off >>= 1)
                ps += __shfl_xor_sync(0xffffffffu, ps, off);
            l_i[i] = l_i[i] * al + ps;
            m_i[i] = nm;
#pragma unroll
            for (int j = 0; j < 4; j++) o[i][j] *= al;
            // stash P for the PV matmul: Ss[key][row]
#pragma unroll
            for (int j = 0; j < 4; j++)
                Ss[(c0 + j) * PS + r0 + i] = s[i][j];
        }
        __syncthreads();

        // ---- O += P V ----
#pragma unroll 8
        for (int kk = 0; kk < 64; kk++) {
            float4 a  = *(const float4*)(Ss + kk * PS + r0);
            float4 vv = *(const float4*)(Vs + kk * PS + c0);
            float ar[4] = {a.x, a.y, a.z, a.w};
            float br[4] = {vv.x, vv.y, vv.z, vv.w};
#pragma unroll
            for (int i = 0; i < 4; i++)
#pragma unroll
                for (int j = 0; j < 4; j++)
                    o[i][j] += ar[i] * br[j];
        }
    }
    __syncthreads();   // last PV reads of Ss done before reuse as Os

    // ---- per-head constants ----
    float bsig = 1.f / (1.f + expf(-beta_[h]));
    float sa, ca;
    sincosf(PI_F * bsig, &sa, &ca);
    float iv  = 1.f / (1.f + expf(-inval[h]));
    float ov  = 1.f / (1.f + expf(-outval[h]));
    float gch = tanhf(chiv[h]);
    float fac = iv * ov * gch;   // rotation is linear: fold iv*ov*g into one factor

    // stage normalized O: Os[row][col]
#pragma unroll
    for (int i = 0; i < 4; i++) {
        float inv = 1.f / l_i[i];
#pragma unroll
        for (int j = 0; j < 4; j++)
            Ss[(r0 + i) * PS + c0 + j] = o[i][j] * inv;
    }
    __syncthreads();

    // rotate halves (j, j+32) and write [B,T,D] combined layout
    float* ob = out + ((size_t)(b * T_SEQ + q0)) * DMODEL + h * DHEAD;
#pragma unroll
    for (int it = 0; it < 8; it++) {
        int p = tid + (it << 8);
        int r = p >> 5;
        int j = p & 31;
        float xr = Ss[r * PS + j];
        float xi = Ss[r * PS + j + 32];
        ob[(size_t)r * DMODEL + j]      = (xr * ca - xi * sa) * fac;
        ob[(size_t)r * DMODEL + j + 32] = (xr * sa + xi * ca) * fac;
    }
}

#define ATTN_SMEM (4 * 64 * PS * sizeof(float))   // 69,632 B

// =========================================================================
extern "C" void kernel_launch(void* const* d_in, const int* in_sizes, int n_in,
                              void* d_out, int out_size)
{
    (void)in_sizes; (void)n_in; (void)out_size;

    const float* x    = (const float*)d_in[0];
    const float* Wq   = (const float*)d_in[1];
    const float* Wk   = (const float*)d_in[2];
    const float* Wv   = (const float*)d_in[3];
    const float* We   = (const float*)d_in[4];
    const float* beta = (const float*)d_in[5];
    const float* ivv  = (const float*)d_in[6];
    const float* ovv  = (const float*)d_in[7];
    const float* chi  = (const float*)d_in[8];
    float* out = (float*)d_out;

    float *qp, *kp, *vp, *ap;
    cudaGetSymbolAddress((void**)&qp, g_q);
    cudaGetSymbolAddress((void**)&kp, g_k);
    cudaGetSymbolAddress((void**)&vp, g_v);
    cudaGetSymbolAddress((void**)&ap, g_ao);

    // Persistent function attribute; set on the (uncaptured) correctness run
    // first, so the captured launches inherit it.
    cudaFuncSetAttribute(attn_kernel, cudaFuncAttributeMaxDynamicSharedMemorySize,
                         (int)ATTN_SMEM);

    dim3 gg(DMODEL / 64, MROWS / 64);   // (16, 64)
    sgemm_nt64<<<gg, 128>>>(x, Wq, qp, MROWS, DMODEL, DMODEL);
    sgemm_nt64<<<gg, 128>>>(x, Wk, kp, MROWS, DMODEL, DMODEL);
    sgemm_nt64<<<gg, 128>>>(x, Wv, vp, MROWS, DMODEL, DMODEL);

    dim3 ga(T_SEQ / 64, NHEADS, BATCH); // (32, 16, 2)
    attn_kernel<<<ga, 256, ATTN_SMEM>>>(qp, kp, vp, beta, ivv, ovv, chi, ap);

    sgemm_nt64<<<gg, 128>>>(ap, We, out, MROWS, DMODEL, DMODEL);
}